// round 6
// baseline (speedup 1.0000x reference)
#include <cuda_runtime.h>
#include <cstdint>

// ---------------------------------------------------------------- constants
#define HW    16384
#define C     256
#define NFG   4096
#define NBG   12288
#define TOPK  20
#define MT    128
#define NT    128
#define FG_TILES (NFG / NT)          // 32
#define NTILES   ((NFG + NBG) / NT)  // 128
#define NCHUNKS  (NTILES * 8)        // 1024 chunks of 32 k

#define THREADS 256                  // 8 warps, warp tile 32x64
#define STAGES  3

// A fragment-packed smem: [ks(32)][rowgrp(8)][lane(32)][reg(4)] = 128 KB
#define AF_FLOATS (32 * 8 * 32 * 4)
// B chunk: 128 rows x 32 k, row stride 40 floats (conflict-free)
#define BPAD 40
#define B_FLOATS (128 * BPAD)                  // 5120 (20 KB)
#define MG_FLOATS (THREADS * TOPK)             // 5120 (20 KB)
#define SMEM_FLOATS (AF_FLOATS + STAGES * B_FLOATS + MG_FLOATS)
#define SMEM_BYTES  (SMEM_FLOATS * 4)          // 212992

// normalized (tf32-rounded) features
__device__ float g_sN[HW * C];     // row-major [pixel][k]
__device__ float g_fgN[NFG * C];   // k-permuted within 8-groups: pairs (k,k+4)
__device__ float g_bgN[NBG * C];

// ---------------------------------------------------------------- helpers
__device__ __forceinline__ float to_tf32(float x) {
    uint32_t u; asm("cvt.rna.tf32.f32 %0, %1;" : "=r"(u) : "f"(x));
    return __uint_as_float(u);
}
__device__ __forceinline__ uint32_t smem_u32(const void* p) {
    uint32_t a;
    asm("{ .reg .u64 t; cvta.to.shared.u64 t, %1; cvt.u32.u64 %0, t; }"
        : "=r"(a) : "l"(p));
    return a;
}
__device__ __forceinline__ void cp_async16(uint32_t dst, const void* src) {
    asm volatile("cp.async.cg.shared.global [%0], [%1], 16;" :: "r"(dst), "l"(src));
}
__device__ __forceinline__ void cp_commit() {
    asm volatile("cp.async.commit_group;" ::: "memory");
}
__device__ __forceinline__ void cp_wait1() {
    asm volatile("cp.async.wait_group 1;" ::: "memory");
}
__device__ __forceinline__ void mma_tf32(float* d, const float* a, float b0, float b1) {
    asm volatile(
        "mma.sync.aligned.m16n8k8.row.col.f32.tf32.tf32.f32 "
        "{%0,%1,%2,%3}, {%4,%5,%6,%7}, {%8,%9}, {%0,%1,%2,%3};"
        : "+f"(d[0]), "+f"(d[1]), "+f"(d[2]), "+f"(d[3])
        : "r"(__float_as_uint(a[0])), "r"(__float_as_uint(a[1])),
          "r"(__float_as_uint(a[2])), "r"(__float_as_uint(a[3])),
          "r"(__float_as_uint(b0)), "r"(__float_as_uint(b1)));
}
__device__ __forceinline__ int kperm(int k) {
    return (k & ~7) | ((k & 3) << 1) | ((k >> 2) & 1);
}
// sorted-descending top list; call only when v > tl[TOPK-1]
__device__ __forceinline__ void topk_insert(float (&tl)[TOPK], float v) {
#pragma unroll
    for (int q = TOPK - 1; q >= 1; q--)
        tl[q] = (v > tl[q - 1]) ? tl[q - 1] : fmaxf(tl[q], v);
    tl[0] = fmaxf(tl[0], v);
}

// ---------------------------------------------------------------- normalize
__global__ void norm_s_kernel(const float* __restrict__ s) {
    int p = blockIdx.x * blockDim.x + threadIdx.x;
    float ss = 0.f;
#pragma unroll 8
    for (int c = 0; c < C; c++) { float v = s[c * HW + p]; ss += v * v; }
    float sc = 1.f / fmaxf(sqrtf(ss), 1e-12f);
#pragma unroll 8
    for (int c = 0; c < C; c++)
        g_sN[p * C + c] = to_tf32(s[c * HW + p] * sc);
}

__global__ void norm_rows_kernel(const float* __restrict__ x, int R, int isBg) {
    float* __restrict__ y = isBg ? g_bgN : g_fgN;
    int gwarp = (blockIdx.x * blockDim.x + threadIdx.x) >> 5;
    int lane  = threadIdx.x & 31;
    int nwarp = (gridDim.x * blockDim.x) >> 5;
    for (int r = gwarp; r < R; r += nwarp) {
        const float* xr = x + (size_t)r * C;
        float v[8]; float ss = 0.f;
#pragma unroll
        for (int j = 0; j < 8; j++) { v[j] = xr[lane + 32 * j]; ss += v[j] * v[j]; }
#pragma unroll
        for (int o = 16; o; o >>= 1) ss += __shfl_xor_sync(0xffffffffu, ss, o);
        float sc = 1.f / fmaxf(sqrtf(ss), 1e-12f);
        float* yr = y + (size_t)r * C;
#pragma unroll
        for (int j = 0; j < 8; j++) {
            int k = lane + 32 * j;
            yr[kperm(k)] = to_tf32(v[j] * sc);
        }
    }
}

// ---------------------------------------------------------------- main kernel
// 8 warps: mwarp = wid>>1 (rows mwarp*32), nwarp = wid&1 (cols nwarp*64).
// Warp tile 32x64: mt in {0,1} (16-row blocks), nt in {0..7} (8-col blocks).
__global__ __launch_bounds__(THREADS, 1) void gemm_topk(float* __restrict__ out) {
    extern __shared__ float sm[];
    float* Af  = sm;
    float* Bsb = Af + AF_FLOATS;       // 3 stage buffers
    float* Mg  = Bsb + STAGES * B_FLOATS;

    const int tid   = threadIdx.x;
    const int lane  = tid & 31;
    const int wid   = tid >> 5;
    const int mwarp = wid >> 1;
    const int nwarp = wid & 1;
    const int g4    = lane >> 2;
    const int t4    = lane & 3;
    const int mb    = blockIdx.x;

    // ---- stage A into fragment layout (once) ----
    {
        const float* Ag = g_sN + (size_t)mb * MT * C;
#pragma unroll
        for (int j = 0; j < 32; j++) {
            int idx = tid + j * THREADS;       // 8192 float4
            int r   = idx >> 6;
            int k4  = idx & 63;
            float4 v = *(const float4*)(Ag + r * C + k4 * 4);
            int base = (((k4 >> 1) * 8 + (r >> 4)) * 128)
                     + ((r & 7) * 4) * 4
                     + ((r >> 3) & 1) + 2 * (k4 & 1);
            Af[base + 0]  = v.x;
            Af[base + 4]  = v.y;
            Af[base + 8]  = v.z;
            Af[base + 12] = v.w;
        }
    }

    // ---- B prefetch into stage buffer ----
    uint32_t bsa = smem_u32(Bsb);
    auto issueB = [&](int ci) {
        if (ci < NCHUNKS) {
            int t  = ci >> 3, kc = ci & 7;
            const float* src = (t < FG_TILES ? g_fgN + (size_t)t * NT * C
                                             : g_bgN + (size_t)(t - FG_TILES) * NT * C)
                               + kc * 32;
            uint32_t sb = bsa + (uint32_t)((ci % STAGES) * B_FLOATS) * 4u;
#pragma unroll
            for (int j = 0; j < 4; j++) {
                int idx = tid + j * THREADS;   // 1024 float4
                int n   = idx >> 3;
                int k4  = idx & 7;
                cp_async16(sb + (uint32_t)(n * BPAD + k4 * 4) * 4u,
                           src + n * C + k4 * 4);
            }
        }
        cp_commit();                           // empty group if past end
    };
    issueB(0);
    issueB(1);

    // ---- top-K state: 4 row-streams per thread, sorted desc in registers ----
    float top[4][TOPK];
#pragma unroll
    for (int p = 0; p < 4; p++)
#pragma unroll
        for (int q = 0; q < TOPK; q++) top[p][q] = -1e30f;

    float acc[2][8][4];
#pragma unroll
    for (int mt = 0; mt < 2; mt++)
#pragma unroll
        for (int nt = 0; nt < 8; nt++)
#pragma unroll
            for (int c = 0; c < 4; c++) acc[mt][nt][c] = 0.f;

#pragma unroll 1
    for (int ci = 0; ci < NCHUNKS; ci++) {
        cp_wait1();                            // chunk ci complete
        __syncthreads();                       // data visible; prev buffer free
        issueB(ci + STAGES - 1);
        const float* Bb = Bsb + (ci % STAGES) * B_FLOATS;

#pragma unroll
        for (int s = 0; s < 4; s++) {
            int ks = (ci & 7) * 4 + s;
            float a[2][4];
#pragma unroll
            for (int mt = 0; mt < 2; mt++) {
                int g = mwarp * 2 + mt;
                float4 v = *(const float4*)&Af[((ks * 8 + g) * 32 + lane) * 4];
                a[mt][0] = v.x; a[mt][1] = v.y; a[mt][2] = v.z; a[mt][3] = v.w;
            }
#pragma unroll
            for (int nt = 0; nt < 8; nt++) {
                int cg = nwarp * 8 + nt;
                float2 b = *(const float2*)&Bb[(cg * 8 + g4) * BPAD + s * 8 + 2 * t4];
                mma_tf32(acc[0][nt], a[0], b.x, b.y);
                mma_tf32(acc[1][nt], a[1], b.x, b.y);
            }
        }

        if ((ci & 7) == 7) {
            // ---- top-K update from this tile's 32 finished sims ----
#pragma unroll
            for (int p = 0; p < 4; p++) {
                const int mt = p >> 1, h = p & 1;
                float mx = -1e30f;
#pragma unroll
                for (int nt = 0; nt < 8; nt++) {
                    mx = fmaxf(mx, acc[mt][nt][2 * h]);
                    mx = fmaxf(mx, acc[mt][nt][2 * h + 1]);
                }
                if (mx > top[p][TOPK - 1]) {
#pragma unroll
                    for (int nt = 0; nt < 8; nt++) {
#pragma unroll
                        for (int cc = 0; cc < 2; cc++) {
                            float v = acc[mt][nt][2 * h + cc];
                            if (v > top[p][TOPK - 1]) topk_insert(top[p], v);
                        }
                    }
                }
            }
#pragma unroll
            for (int mt = 0; mt < 2; mt++)
#pragma unroll
                for (int nt = 0; nt < 8; nt++)
#pragma unroll
                    for (int c = 0; c < 4; c++) acc[mt][nt][c] = 0.f;

            int t = ci >> 3;
            if (t == FG_TILES - 1 || t == NTILES - 1) {
                float* obase = out + (t == FG_TILES - 1 ? 0 : HW) + mb * MT;
#pragma unroll
                for (int p = 0; p < 4; p++) {
                    const int mt = p >> 1, h = p & 1;
#pragma unroll
                    for (int q = 0; q < TOPK; q++) Mg[tid * TOPK + q] = top[p][q];
                    __syncthreads();
                    if (tid < 32) {
                        int mw = tid >> 3, rg = tid & 7;
                        int row = mw * 32 + mt * 16 + h * 8 + rg;
                        float best[TOPK];
#pragma unroll
                        for (int q = 0; q < TOPK; q++) best[q] = -1e30f;
                        for (int nw = 0; nw < 2; nw++) {
                            for (int l = 0; l < 4; l++) {
                                int slot = (mw * 2 + nw) * 32 + rg * 4 + l;
                                for (int q = 0; q < TOPK; q++) {
                                    float v = Mg[slot * TOPK + q];
                                    if (v > best[TOPK - 1]) topk_insert(best, v);
                                }
                            }
                        }
                        float ssum = 0.f;
#pragma unroll
                        for (int q = 0; q < TOPK; q++) ssum += best[q];
                        obase[row] = ssum * (1.0f / TOPK);
                    }
                    __syncthreads();
#pragma unroll
                    for (int q = 0; q < TOPK; q++) top[p][q] = -1e30f;
                }
            }
        }
    }
}

// ---------------------------------------------------------------- launch
extern "C" void kernel_launch(void* const* d_in, const int* in_sizes, int n_in,
                              void* d_out, int out_size) {
    const float* s  = (const float*)d_in[0];
    const float* fg = (const float*)d_in[1];
    const float* bg = (const float*)d_in[2];
    float* out = (float*)d_out;

    cudaFuncSetAttribute(gemm_topk,
                         cudaFuncAttributeMaxDynamicSharedMemorySize, SMEM_BYTES);

    norm_s_kernel<<<HW / 128, 128>>>(s);
    norm_rows_kernel<<<128, 256>>>(fg, NFG, 0);
    norm_rows_kernel<<<128, 256>>>(bg, NBG, 1);
    gemm_topk<<<HW / MT, THREADS, SMEM_BYTES>>>(out);
}

// round 7
// speedup vs baseline: 1.3578x; 1.3578x over previous
#include <cuda_runtime.h>
#include <cuda_bf16.h>
#include <cstdint>

// ---------------------------------------------------------------- constants
#define HW    16384
#define C     256
#define NFG   4096
#define NBG   12288
#define TOPK  20
#define MT    128
#define NT    128
#define FG_TILES 32
#define NTILES   128
#define CHUNK_K  64
#define CPT      4                    // chunks per tile
#define NCHUNKS  (NTILES * CPT)       // 512

#define THREADS 256
#define STAGES  3

// A fragment-packed: [ks(16)][rowgrp(8)][lane(32)][4 x b32] = 64 KB
#define AF_U32   (16 * 8 * 32 * 4)
// B chunk: 128 rows x 64 k bf16, row stride 80 halves (160 B, conflict-free)
#define BPADH    80
#define B_HALFS  (128 * BPADH)        // 10240 halves = 20 KB / stage
#define MG_FLOATS (THREADS * TOPK)    // 20 KB
#define SMEM_BYTES (AF_U32 * 4 + STAGES * B_HALFS * 2 + MG_FLOATS * 4) // 147456

// normalized bf16 features
__device__ __nv_bfloat16 g_sN[HW * C];     // row-major [pixel][k] (A path)
__device__ __nv_bfloat16 g_fgN[NFG * C];   // k-permuted within 16-groups (B path)
__device__ __nv_bfloat16 g_bgN[NBG * C];

// ---------------------------------------------------------------- helpers
__device__ __forceinline__ uint32_t smem_u32(const void* p) {
    uint32_t a;
    asm("{ .reg .u64 t; cvta.to.shared.u64 t, %1; cvt.u32.u64 %0, t; }"
        : "=r"(a) : "l"(p));
    return a;
}
__device__ __forceinline__ void cp_async16(uint32_t dst, const void* src) {
    asm volatile("cp.async.cg.shared.global [%0], [%1], 16;" :: "r"(dst), "l"(src));
}
__device__ __forceinline__ void cp_commit() {
    asm volatile("cp.async.commit_group;" ::: "memory");
}
__device__ __forceinline__ void cp_wait1() {
    asm volatile("cp.async.wait_group 1;" ::: "memory");
}
__device__ __forceinline__ void mma_bf16(float* d, const uint32_t* a,
                                         uint32_t b0, uint32_t b1) {
    asm volatile(
        "mma.sync.aligned.m16n8k16.row.col.f32.bf16.bf16.f32 "
        "{%0,%1,%2,%3}, {%4,%5,%6,%7}, {%8,%9}, {%0,%1,%2,%3};"
        : "+f"(d[0]), "+f"(d[1]), "+f"(d[2]), "+f"(d[3])
        : "r"(a[0]), "r"(a[1]), "r"(a[2]), "r"(a[3]), "r"(b0), "r"(b1));
}
// B k-permutation within 16-group: order (0,1),(8,9),(2,3),(10,11),(4,5),(12,13),(6,7),(14,15)
__device__ __forceinline__ int kperm16(int k) {
    return (k & ~15) | (((k & 7) >> 1) << 2) | (((k >> 3) & 1) << 1) | (k & 1);
}
// sorted-descending top list; call only when v > tl[TOPK-1]
__device__ __forceinline__ void topk_insert(float (&tl)[TOPK], float v) {
#pragma unroll
    for (int q = TOPK - 1; q >= 1; q--)
        tl[q] = (v > tl[q - 1]) ? tl[q - 1] : fmaxf(tl[q], v);
    tl[0] = fmaxf(tl[0], v);
}

// ---------------------------------------------------------------- normalize
__global__ void norm_s_kernel(const float* __restrict__ s) {
    int p = blockIdx.x * blockDim.x + threadIdx.x;
    float ss = 0.f;
#pragma unroll 8
    for (int c = 0; c < C; c++) { float v = s[c * HW + p]; ss += v * v; }
    float sc = 1.f / fmaxf(sqrtf(ss), 1e-12f);
#pragma unroll 8
    for (int c = 0; c < C; c++)
        g_sN[p * C + c] = __float2bfloat16_rn(s[c * HW + p] * sc);
}

__global__ void norm_rows_kernel(const float* __restrict__ x, int R, int isBg) {
    __nv_bfloat16* __restrict__ y = isBg ? g_bgN : g_fgN;
    int gwarp = (blockIdx.x * blockDim.x + threadIdx.x) >> 5;
    int lane  = threadIdx.x & 31;
    int nwarp = (gridDim.x * blockDim.x) >> 5;
    for (int r = gwarp; r < R; r += nwarp) {
        const float* xr = x + (size_t)r * C;
        float v[8]; float ss = 0.f;
#pragma unroll
        for (int j = 0; j < 8; j++) { v[j] = xr[lane + 32 * j]; ss += v[j] * v[j]; }
#pragma unroll
        for (int o = 16; o; o >>= 1) ss += __shfl_xor_sync(0xffffffffu, ss, o);
        float sc = 1.f / fmaxf(sqrtf(ss), 1e-12f);
        __nv_bfloat16* yr = y + (size_t)r * C;
#pragma unroll
        for (int j = 0; j < 8; j++) {
            int k = lane + 32 * j;
            yr[kperm16(k)] = __float2bfloat16_rn(v[j] * sc);
        }
    }
}

// ---------------------------------------------------------------- main kernel
// 8 warps: mwarp = wid>>1 (rows mwarp*32), nwarp = wid&1 (cols nwarp*64).
// Warp tile 32x64 via m16n8k16 bf16: mt in {0,1}, nt in {0..7}.
__global__ __launch_bounds__(THREADS, 1) void gemm_topk(float* __restrict__ out) {
    extern __shared__ char smc[];
    uint32_t*       AfU = (uint32_t*)smc;                       // fragment A
    __nv_bfloat16*  Bsh = (__nv_bfloat16*)(smc + AF_U32 * 4);   // 3 stages
    float*          Mg  = (float*)(smc + AF_U32 * 4 + STAGES * B_HALFS * 2);

    const int tid   = threadIdx.x;
    const int lane  = tid & 31;
    const int wid   = tid >> 5;
    const int mwarp = wid >> 1;
    const int nwarp = wid & 1;
    const int g4    = lane >> 2;
    const int t4    = lane & 3;
    const int mb    = blockIdx.x;

    // ---- stage A into m16n8k16 fragment layout (once) ----
    {
        const uint4* Ag = (const uint4*)(g_sN + (size_t)mb * MT * C);  // 32 uint4/row
#pragma unroll
        for (int j = 0; j < 16; j++) {
            int idx = tid + j * THREADS;       // 4096 uint4
            int r   = idx >> 5;
            int j8  = idx & 31;                // k0 = j8*8
            uint4 v = Ag[idx];
            int ks     = j8 >> 1;              // k16 index
            int khalf  = j8 & 1;
            int rowgrp = r >> 4, g4r = r & 7, rowhalf = (r >> 3) & 1;
            int reg  = rowhalf + 2 * khalf;
            uint32_t* base = AfU + ((ks * 8 + rowgrp) * 32) * 4 + reg;
            uint32_t w[4] = { v.x, v.y, v.z, v.w };
#pragma unroll
            for (int p = 0; p < 4; p++)
                base[(g4r * 4 + p) * 4] = w[p];   // pair p -> lane g4r*4+p
        }
    }

    // ---- B prefetch into stage buffer (chunk = 64 k) ----
    uint32_t bsa = smem_u32(Bsh);
    auto issueB = [&](int ci) {
        if (ci < NCHUNKS) {
            int t  = ci >> 2, kc = ci & 3;
            const __nv_bfloat16* src =
                (t < FG_TILES ? g_fgN + (size_t)t * NT * C
                              : g_bgN + (size_t)(t - FG_TILES) * NT * C)
                + kc * CHUNK_K;
            uint32_t sb = bsa + (uint32_t)((ci % STAGES) * B_HALFS) * 2u;
#pragma unroll
            for (int j = 0; j < 4; j++) {
                int idx = tid + j * THREADS;   // 1024 x 16B
                int n   = idx >> 3;
                int jj  = idx & 7;
                cp_async16(sb + (uint32_t)(n * BPADH * 2 + jj * 16),
                           (const char*)src + (size_t)n * C * 2 + jj * 16);
            }
        }
        cp_commit();
    };
    issueB(0);
    issueB(1);

    // ---- top-K state: 4 row-streams, sorted desc in registers + row thr ----
    float top[4][TOPK]; float thr[4];
#pragma unroll
    for (int p = 0; p < 4; p++) {
#pragma unroll
        for (int q = 0; q < TOPK; q++) top[p][q] = -1e30f;
        thr[p] = -1e30f;
    }

    float acc[2][8][4];
#pragma unroll
    for (int mt = 0; mt < 2; mt++)
#pragma unroll
        for (int nt = 0; nt < 8; nt++)
#pragma unroll
            for (int c = 0; c < 4; c++) acc[mt][nt][c] = 0.f;

#pragma unroll 1
    for (int ci = 0; ci < NCHUNKS; ci++) {
        cp_wait1();
        __syncthreads();
        issueB(ci + STAGES - 1);
        const __nv_bfloat16* Bb = Bsh + (ci % STAGES) * B_HALFS;

#pragma unroll
        for (int s = 0; s < 4; s++) {
            int ks = (ci & 3) * 4 + s;
            uint32_t a[2][4];
#pragma unroll
            for (int mt = 0; mt < 2; mt++) {
                uint4 v = *(const uint4*)&AfU[((ks * 8 + (mwarp * 2 + mt)) * 32 + lane) * 4];
                a[mt][0] = v.x; a[mt][1] = v.y; a[mt][2] = v.z; a[mt][3] = v.w;
            }
#pragma unroll
            for (int nt = 0; nt < 8; nt++) {
                int cg = nwarp * 8 + nt;
                uint2 b = *(const uint2*)(Bb + (cg * 8 + g4) * BPADH + s * 16 + t4 * 4);
                mma_bf16(acc[0][nt], a[0], b.x, b.y);
                mma_bf16(acc[1][nt], a[1], b.x, b.y);
            }
        }

        if ((ci & 3) == 3) {                   // tile finished
            // ---- top-K update, gated by row-level threshold ----
#pragma unroll
            for (int p = 0; p < 4; p++) {
                const int mt = p >> 1, h = p & 1;
                float mx = -1e30f;
#pragma unroll
                for (int nt = 0; nt < 8; nt++) {
                    mx = fmaxf(mx, acc[mt][nt][2 * h]);
                    mx = fmaxf(mx, acc[mt][nt][2 * h + 1]);
                }
                if (mx > thr[p]) {
#pragma unroll
                    for (int nt = 0; nt < 8; nt++) {
#pragma unroll
                        for (int cc = 0; cc < 2; cc++) {
                            float v = acc[mt][nt][2 * h + cc];
                            if (v > thr[p]) topk_insert(top[p], v);
                        }
                    }
                }
                // refresh row threshold = max of the 4 sub-lists' 20th-best
                float t19 = top[p][TOPK - 1];
                t19 = fmaxf(t19, __shfl_xor_sync(0xffffffffu, t19, 1));
                t19 = fmaxf(t19, __shfl_xor_sync(0xffffffffu, t19, 2));
                thr[p] = t19;
            }
#pragma unroll
            for (int mt = 0; mt < 2; mt++)
#pragma unroll
                for (int nt = 0; nt < 8; nt++)
#pragma unroll
                    for (int c = 0; c < 4; c++) acc[mt][nt][c] = 0.f;

            int t = ci >> 2;
            if (t == FG_TILES - 1 || t == NTILES - 1) {
                float* obase = out + (t == FG_TILES - 1 ? 0 : HW) + mb * MT;
#pragma unroll
                for (int p = 0; p < 4; p++) {
                    const int mt = p >> 1, h = p & 1;
#pragma unroll
                    for (int q = 0; q < TOPK; q++) Mg[tid * TOPK + q] = top[p][q];
                    __syncthreads();
                    if (tid < 32) {
                        int mw = tid >> 3, rg = tid & 7;
                        int row = mw * 32 + mt * 16 + h * 8 + rg;
                        float best[TOPK];
#pragma unroll
                        for (int q = 0; q < TOPK; q++) best[q] = -1e30f;
                        for (int nw = 0; nw < 2; nw++) {
                            for (int l = 0; l < 4; l++) {
                                int slot = (mw * 2 + nw) * 32 + rg * 4 + l;
                                for (int q = 0; q < TOPK; q++) {
                                    float v = Mg[slot * TOPK + q];
                                    if (v > best[TOPK - 1]) topk_insert(best, v);
                                }
                            }
                        }
                        float ssum = 0.f;
#pragma unroll
                        for (int q = 0; q < TOPK; q++) ssum += best[q];
                        obase[row] = ssum * (1.0f / TOPK);
                    }
                    __syncthreads();
#pragma unroll
                    for (int q = 0; q < TOPK; q++) top[p][q] = -1e30f;
                    thr[p] = -1e30f;
                }
            }
        }
    }
}

// ---------------------------------------------------------------- launch
extern "C" void kernel_launch(void* const* d_in, const int* in_sizes, int n_in,
                              void* d_out, int out_size) {
    const float* s  = (const float*)d_in[0];
    const float* fg = (const float*)d_in[1];
    const float* bg = (const float*)d_in[2];
    float* out = (float*)d_out;

    cudaFuncSetAttribute(gemm_topk,
                         cudaFuncAttributeMaxDynamicSharedMemorySize, SMEM_BYTES);

    norm_s_kernel<<<HW / 128, 128>>>(s);
    norm_rows_kernel<<<128, 256>>>(fg, NFG, 0);
    norm_rows_kernel<<<128, 256>>>(bg, NBG, 1);
    gemm_topk<<<HW / MT, THREADS, SMEM_BYTES>>>(out);
}